// round 4
// baseline (speedup 1.0000x reference)
#include <cuda_runtime.h>

// Problem constants: B=2, C=128, IC=64, W=H=32, Z=128, nz=64
// n = B*W*H = 2048 z-line tiles of x: (C=128) x (Z=128), z contiguous.

#define N_TILES   2048
#define THREADS   512

typedef unsigned long long ull;

// ---- packed f32x2 helpers (SASS FFMA2 — only reachable via PTX) ----
__device__ __forceinline__ ull pk2(float lo, float hi) {
    ull r;
    asm("mov.b64 %0, {%1, %2};" : "=l"(r) : "f"(lo), "f"(hi));
    return r;
}
__device__ __forceinline__ void fma2(ull& d, ull a, ull b) {
    asm("fma.rn.f32x2 %0, %1, %2, %3;" : "=l"(d) : "l"(a), "l"(b), "l"(d));
}
__device__ __forceinline__ float2 upk2(ull v) {
    float2 r;
    asm("mov.b64 {%0, %1}, %2;" : "=f"(r.x), "=f"(r.y) : "l"(v));
    return r;
}

// ---- device-global precomputed buffers ----
__device__ float d_vt[128];       // cat_w[:64]^T @ theta_w  (collapses theta conv)
__device__ float d_ct;            // cat_w[:64] . theta_b
__device__ float d_alpha[128];    // bn_g / sqrt(bn_v + eps)
__device__ float d_beta[128];     // (W_b - bn_m)*alpha + bn_b
__device__ float d_gpwI[16384];   // row Ci: interleaved pairs (g_w[oc][Ci], phi_w[oc][Ci]) oc 0..63
__device__ float d_WwT[8192];     // row c:  [W_w[Co][c] for Co 0..127] (Co-pairs adjacent)

__global__ void setup_kernel(const float* __restrict__ theta_w,
                             const float* __restrict__ theta_b,
                             const float* __restrict__ cat_w,
                             const float* __restrict__ W_b,
                             const float* __restrict__ bn_g,
                             const float* __restrict__ bn_b,
                             const float* __restrict__ bn_m,
                             const float* __restrict__ bn_v,
                             const float* __restrict__ g_w,
                             const float* __restrict__ phi_w,
                             const float* __restrict__ W_w)
{
    int tid = threadIdx.x;  // 256 threads, 1 block
    if (tid < 128) {
        float s = 0.f;
        for (int ic = 0; ic < 64; ic++) s += cat_w[ic] * theta_w[ic * 128 + tid];
        d_vt[tid] = s;
        float a = bn_g[tid] * rsqrtf(bn_v[tid] + 1e-5f);
        d_alpha[tid] = a;
        d_beta[tid]  = (W_b[tid] - bn_m[tid]) * a + bn_b[tid];
    }
    if (tid == 0) {
        float s = 0.f;
        for (int ic = 0; ic < 64; ic++) s += cat_w[ic] * theta_b[ic];
        d_ct = s;
    }
    for (int idx = tid; idx < 8192; idx += 256) {
        int oc = idx >> 7, Ci = idx & 127;
        d_gpwI[Ci * 128 + oc * 2]     = g_w[idx];
        d_gpwI[Ci * 128 + oc * 2 + 1] = phi_w[idx];
    }
    for (int idx = tid; idx < 8192; idx += 256) {
        int Co = idx >> 6, c = idx & 63;
        d_WwT[c * 128 + Co] = W_w[idx];
    }
}

// Shared memory layout (floats)
#define OFF_XS     0        // 16384 : x tile [C=128][Z=128]
#define OFF_GPWI   16384    // 16384 : interleaved (g,phi) weights [Ci=128][128]
#define OFF_WWT    32768    //  8192 : W weights transposed [c=64][Co=128]
#define OFF_YS     40960    //  8192 : y transposed [c=64][i=128]
#define OFF_GP     49152    //  4352 : pooled g (pre-scaled 1/64) [j=64][stride 68]
#define GP_STRIDE  68
#define OFF_BBP    53504    //   512 : per-ocblock partials of bb [blk=8][j=64]
#define OFF_A      54016    //   128 : a[i]
#define OFF_BB     54144    //    64 : bb[j]
#define OFF_VT     54208    //   128
#define OFF_WP     54336    //    64 : cat_w[64:]
#define OFF_GB     54400    //    64 : g_b
#define OFF_PB     54464    //    64 : phi_b
#define OFF_AL     54528    //   128 : alpha
#define OFF_BE     54656    //   128 : beta
#define SMEM_FLOATS 54784
#define SMEM_BYTES (SMEM_FLOATS * 4)   // 219136

__global__ void __launch_bounds__(THREADS, 1)
nonlocal_kernel(const float* __restrict__ x,
                const float* __restrict__ g_b,
                const float* __restrict__ phi_b,
                const float* __restrict__ cat_w,
                float* __restrict__ out)
{
    extern __shared__ float sm[];
    float*       xs   = sm + OFF_XS;
    float*       gp   = sm + OFF_GP;
    float*       bbp  = sm + OFF_BBP;
    float*       a_s  = sm + OFF_A;
    float*       bb_s = sm + OFF_BB;
    float*       vt_s = sm + OFF_VT;
    float*       wp_s = sm + OFF_WP;
    float*       gb_s = sm + OFF_GB;
    float*       pb_s = sm + OFF_PB;
    float*       al_s = sm + OFF_AL;
    float*       be_s = sm + OFF_BE;
    float4*      xs4   = (float4*)(sm + OFF_XS);
    float4*      gpwI4 = (float4*)(sm + OFF_GPWI);
    float4*      WwT4  = (float4*)(sm + OFF_WWT);
    float4*      ys4   = (float4*)(sm + OFF_YS);

    const int tid  = threadIdx.x;
    const int lane = tid & 31;
    const int wid  = tid >> 5;       // 0..15

    const int n  = blockIdx.x;       // tile id
    const int b  = n >> 10;
    const int wh = n & 1023;

    // x[b][c][wh][z]: float offset ((b*128 + c)*1024 + wh)*128 + z
    const float4* xg = (const float4*)(x + (((size_t)(b * 128) * 1024 + wh) * 128));

    // ---- stage A: loads (coalesced float4, conflict-free smem stores) ----
    #pragma unroll
    for (int it = 0; it < 8; it++) {
        int idx = it * 512 + tid;              // 4096 float4
        int c = idx >> 5, zq = idx & 31;
        xs4[idx] = xg[(size_t)c * 32768 + zq]; // row stride 131072 floats
    }
    {
        const float4* gg = (const float4*)d_gpwI;
        #pragma unroll
        for (int it = 0; it < 8; it++) gpwI4[it * 512 + tid] = gg[it * 512 + tid];
        const float4* wg = (const float4*)d_WwT;
        #pragma unroll
        for (int it = 0; it < 4; it++)  WwT4[it * 512 + tid] = wg[it * 512 + tid];
    }
    if (tid < 128) { vt_s[tid] = d_vt[tid]; al_s[tid] = d_alpha[tid]; be_s[tid] = d_beta[tid]; }
    if (tid < 64)  { wp_s[tid] = cat_w[64 + tid]; gb_s[tid] = g_b[tid]; pb_s[tid] = phi_b[tid]; }
    __syncthreads();

    // ---- stage B: g+phi conv, (g,phi) packed in f32x2 lanes ----
    // warp: oc block = (wid&7)*8 ; z half = wid>>3 ; lane -> 2 z values
    {
        const int ocb = (wid & 7) * 8;
        const int zh  = wid >> 3;
        const int z0  = zh * 64 + lane * 2;
        const bool do_a = (ocb == 0);

        ull acc[2][8];                 // [z of pair][oc], lanes = (g, phi)
        #pragma unroll
        for (int k = 0; k < 2; k++)
            #pragma unroll
            for (int o = 0; o < 8; o++) acc[k][o] = 0ULL;
        float aa0 = 0.f, aa1 = 0.f;

        const ulonglong2* wbase = (const ulonglong2*)(sm + OFF_GPWI + ocb * 2);

        #pragma unroll 2
        for (int Ci = 0; Ci < 128; Ci++) {
            float2 xv = *(const float2*)(xs + Ci * 128 + z0);   // LDS.64, conflict-free
            ull xd0 = pk2(xv.x, xv.x);
            ull xd1 = pk2(xv.y, xv.y);
            const ulonglong2* wrow = (const ulonglong2*)((const char*)wbase + Ci * 512);
            ulonglong2 w0 = wrow[0], w1 = wrow[1], w2 = wrow[2], w3 = wrow[3]; // broadcast
            ull w[8] = {w0.x, w0.y, w1.x, w1.y, w2.x, w2.y, w3.x, w3.y};
            #pragma unroll
            for (int o = 0; o < 8; o++) {
                fma2(acc[0][o], xd0, w[o]);
                fma2(acc[1][o], xd1, w[o]);
            }
            if (do_a) {
                float v = vt_s[Ci];
                aa0 = fmaf(v, xv.x, aa0);
                aa1 = fmaf(v, xv.y, aa1);
            }
        }

        // epilogue: pool the thread's z-pair -> j, bias, scale g by 1/64, bb partials
        const int j = zh * 32 + lane;
        float part = 0.f;
        #pragma unroll
        for (int o = 0; o < 8; o++) {
            float2 A = upk2(acc[0][o]);   // (g_z0, p_z0)
            float2 Bv = upk2(acc[1][o]);  // (g_z1, p_z1)
            float gmax = fmaxf(A.x, Bv.x);
            float pmax = fmaxf(A.y, Bv.y);
            gp[j * GP_STRIDE + ocb + o] = (gmax + gb_s[ocb + o]) * 0.015625f;
            part = fmaf(wp_s[ocb + o], pmax + pb_s[ocb + o], part);
        }
        bbp[(wid & 7) * 64 + j] = part;
        if (do_a) {
            float ct = d_ct;
            a_s[z0]     = aa0 + ct;
            a_s[z0 + 1] = aa1 + ct;
        }
    }
    __syncthreads();

    if (tid < 64) {  // deterministic reduction of bb over the 8 oc-blocks
        float s = 0.f;
        #pragma unroll
        for (int o8 = 0; o8 < 8; o8++) s += bbp[o8 * 64 + tid];
        bb_s[tid] = s;
    }
    __syncthreads();

    // ---- stage C: y[i][c] = sum_j relu(a[i]+bb[j]) * gp[j][c]  (gp pre-scaled) ----
    // warp -> c block of 4 (16 warps cover c=64) ; lane -> i = 4*lane..+3
    {
        const int cb = wid * 4;
        ull ya[4][2];                 // [i k][c pair]
        #pragma unroll
        for (int k = 0; k < 4; k++) { ya[k][0] = 0ULL; ya[k][1] = 0ULL; }

        float4 av = ((const float4*)a_s)[lane];
        float ak[4] = {av.x, av.y, av.z, av.w};

        #pragma unroll 4
        for (int j = 0; j < 64; j++) {
            float bj = bb_s[j];
            ull f2_[4];
            #pragma unroll
            for (int k = 0; k < 4; k++) {
                float f = fmaxf(ak[k] + bj, 0.f);
                f2_[k] = pk2(f, f);
            }
            ulonglong2 gq = *(const ulonglong2*)(gp + j * GP_STRIDE + cb);  // broadcast
            ull gv[2] = {gq.x, gq.y};
            #pragma unroll
            for (int k = 0; k < 4; k++) {
                fma2(ya[k][0], f2_[k], gv[0]);
                fma2(ya[k][1], f2_[k], gv[1]);
            }
        }
        // ys stored transposed: [c][i], i contiguous
        #pragma unroll
        for (int cp = 0; cp < 2; cp++) {
            float2 e0 = upk2(ya[0][cp]), e1 = upk2(ya[1][cp]);
            float2 e2 = upk2(ya[2][cp]), e3 = upk2(ya[3][cp]);
            ys4[(cb + 2 * cp)     * 32 + lane] = make_float4(e0.x, e1.x, e2.x, e3.x);
            ys4[(cb + 2 * cp + 1) * 32 + lane] = make_float4(e0.y, e1.y, e2.y, e3.y);
        }
    }
    __syncthreads();

    // ---- stage D: out[Co][i] = alpha*(sum_c W[Co][c]*y[i][c]) + beta + x[Co][i] ----
    // warp -> Co block of 8 (16 warps cover 128) packed as 4 Co-pairs ; lane -> i=4*lane..+3
    {
        const int Cb = wid * 8;
        ull oa[4][4];                 // [Co pair][i k], lanes = (Co, Co+1)
        #pragma unroll
        for (int cp = 0; cp < 4; cp++)
            #pragma unroll
            for (int k = 0; k < 4; k++) oa[cp][k] = 0ULL;

        #pragma unroll 2
        for (int c = 0; c < 64; c++) {
            float4 yv = ys4[c * 32 + lane];          // LDS.128 lane-varying, conflict-free
            ull yd[4] = {pk2(yv.x, yv.x), pk2(yv.y, yv.y),
                         pk2(yv.z, yv.z), pk2(yv.w, yv.w)};
            const ulonglong2* wrow = (const ulonglong2*)(sm + OFF_WWT + c * 128 + Cb);
            ulonglong2 q0 = wrow[0], q1 = wrow[1];   // broadcast, Co-pairs natural
            ull wv[4] = {q0.x, q0.y, q1.x, q1.y};
            #pragma unroll
            for (int cp = 0; cp < 4; cp++)
                #pragma unroll
                for (int k = 0; k < 4; k++)
                    fma2(oa[cp][k], wv[cp], yd[k]);
        }

        float4* out4 = (float4*)out;
        #pragma unroll
        for (int cp = 0; cp < 4; cp++) {
            float2 e0 = upk2(oa[cp][0]), e1 = upk2(oa[cp][1]);
            float2 e2 = upk2(oa[cp][2]), e3 = upk2(oa[cp][3]);
            int CoA = Cb + 2 * cp, CoB = CoA + 1;
            {
                float al = al_s[CoA], be = be_s[CoA];
                float4 xv = xs4[CoA * 32 + lane];
                float4 r;
                r.x = fmaf(e0.x, al, be) + xv.x;
                r.y = fmaf(e1.x, al, be) + xv.y;
                r.z = fmaf(e2.x, al, be) + xv.z;
                r.w = fmaf(e3.x, al, be) + xv.w;
                out4[((size_t)(b * 128 + CoA) * 1024 + wh) * 32 + lane] = r;
            }
            {
                float al = al_s[CoB], be = be_s[CoB];
                float4 xv = xs4[CoB * 32 + lane];
                float4 r;
                r.x = fmaf(e0.y, al, be) + xv.x;
                r.y = fmaf(e1.y, al, be) + xv.y;
                r.z = fmaf(e2.y, al, be) + xv.z;
                r.w = fmaf(e3.y, al, be) + xv.w;
                out4[((size_t)(b * 128 + CoB) * 1024 + wh) * 32 + lane] = r;
            }
        }
    }
}

extern "C" void kernel_launch(void* const* d_in, const int* in_sizes, int n_in,
                              void* d_out, int out_size)
{
    const float* x       = (const float*)d_in[0];
    const float* g_w     = (const float*)d_in[1];
    const float* g_b     = (const float*)d_in[2];
    const float* theta_w = (const float*)d_in[3];
    const float* theta_b = (const float*)d_in[4];
    const float* phi_w   = (const float*)d_in[5];
    const float* phi_b   = (const float*)d_in[6];
    const float* cat_w   = (const float*)d_in[7];
    const float* W_w     = (const float*)d_in[8];
    const float* W_b     = (const float*)d_in[9];
    const float* bn_g    = (const float*)d_in[10];
    const float* bn_b    = (const float*)d_in[11];
    const float* bn_m    = (const float*)d_in[12];
    const float* bn_v    = (const float*)d_in[13];

    cudaFuncSetAttribute(nonlocal_kernel,
                         cudaFuncAttributeMaxDynamicSharedMemorySize, SMEM_BYTES);

    setup_kernel<<<1, 256>>>(theta_w, theta_b, cat_w, W_b,
                             bn_g, bn_b, bn_m, bn_v, g_w, phi_w, W_w);
    nonlocal_kernel<<<N_TILES, THREADS, SMEM_BYTES>>>(x, g_b, phi_b, cat_w,
                                                      (float*)d_out);
}

// round 6
// speedup vs baseline: 1.9457x; 1.9457x over previous
#include <cuda_runtime.h>
#include <cstdint>

// B=2, C=128, IC=64, W=H=32, Z=128, nz=64. 2048 tiles of x[C=128][Z=128].
// Per tile, via warp-level tf32 mma.sync (m16n8k8, base sm_103 target — tcgen05 is
// 'a'-gated and this toolchain emits .target sm_103):
//   GEMM1 D1[o=128][z=128] = Wgp[o][Ci] @ x[Ci][z]     (g rows 0..63, phi rows 64..127)
//   epi1 (register-local): pool z-pairs; g -> gp[j][c]/64, phi -> bb[j]; a[z]=vt.x scalar
//   GEMM2 D2[z=128][c=64]  = f[z][j] @ gp[j][c],  f = relu(a+bb)
//   GEMM3 D3[z=128][Co=128]= y[z][c] @ Ww[Co][c]
//   epi3: out = D3*alpha + beta + x

#define N_TILES 2048
#define THREADS 256

__device__ __forceinline__ float to_tf32(float v) {
    uint32_t u; asm("cvt.rna.tf32.f32 %0, %1;" : "=r"(u) : "f"(v));
    return __uint_as_float(u);
}
__device__ __forceinline__ void mma8(float* d, uint32_t a0, uint32_t a1, uint32_t a2,
                                     uint32_t a3, uint32_t b0, uint32_t b1) {
    asm volatile("mma.sync.aligned.m16n8k8.row.col.f32.tf32.tf32.f32 "
                 "{%0,%1,%2,%3}, {%4,%5,%6,%7}, {%8,%9}, {%0,%1,%2,%3};"
                 : "+f"(d[0]), "+f"(d[1]), "+f"(d[2]), "+f"(d[3])
                 : "r"(a0), "r"(a1), "r"(a2), "r"(a3), "r"(b0), "r"(b1));
}

// ---- precomputed globals ----
__device__ float d_vt[128];      // cat_w[:64]^T @ theta_w   (theta conv collapsed)
__device__ float d_ct;           // cat_w[:64] . theta_b
__device__ float d_alpha[128];   // bn_g / sqrt(bn_v+eps)
__device__ float d_beta[128];    // (W_b - bn_m)*alpha + bn_b
__device__ float d_A1f[16384];   // Wgp fragment-ordered: [strip8][ks16][lane32][r4]
__device__ float d_WwB[8192];    // Ww  fragment-ordered: [ks8][nt16][lane32][r2]

__global__ void setup_kernel(const float* __restrict__ theta_w,
                             const float* __restrict__ theta_b,
                             const float* __restrict__ cat_w,
                             const float* __restrict__ W_b,
                             const float* __restrict__ bn_g,
                             const float* __restrict__ bn_b,
                             const float* __restrict__ bn_m,
                             const float* __restrict__ bn_v,
                             const float* __restrict__ g_w,
                             const float* __restrict__ phi_w,
                             const float* __restrict__ W_w)
{
    int tid = threadIdx.x;  // 256
    if (tid < 128) {
        float s = 0.f;
        for (int ic = 0; ic < 64; ic++) s += cat_w[ic] * theta_w[ic * 128 + tid];
        d_vt[tid] = s;
        float a = bn_g[tid] * rsqrtf(bn_v[tid] + 1e-5f);
        d_alpha[tid] = a;
        d_beta[tid]  = (W_b[tid] - bn_m[tid]) * a + bn_b[tid];
    }
    if (tid == 0) {
        float s = 0.f;
        for (int ic = 0; ic < 64; ic++) s += cat_w[ic] * theta_b[ic];
        d_ct = s;
    }
    // A fragment order for GEMM1 (m16n8k8 row-major A):
    // a0:(row,col) a1:(row+8,col) a2:(row,col+4) a3:(row+8,col+4)
    for (int idx = tid; idx < 16384; idx += 256) {
        int r = idx & 3, lane = (idx >> 2) & 31, ks = (idx >> 7) & 15, s = idx >> 11;
        int o  = s * 16 + (lane >> 2) + (r & 1) * 8;
        int Ci = ks * 8 + (lane & 3) + ((r >> 1) & 1) * 4;
        float v = (o < 64) ? g_w[o * 128 + Ci] : phi_w[(o - 64) * 128 + Ci];
        d_A1f[idx] = to_tf32(v);
    }
    // B fragment order for GEMM3: b0:(k,n) b1:(k+4,n); k=c, n=Co
    for (int idx = tid; idx < 8192; idx += 256) {
        int r = idx & 1, lane = (idx >> 1) & 31, nt = (idx >> 6) & 15, ks = idx >> 10;
        int c  = ks * 8 + (lane & 3) + r * 4;
        int Co = nt * 8 + (lane >> 2);
        d_WwB[idx] = to_tf32(W_w[Co * 64 + c]);
    }
}

// ---- smem layout (floats); pads chosen for conflict-free frag loads ----
#define OFF_X    0        // x [Ci=128][pad 136]  (136 % 32 == 8)
#define OFF_A1   17408    // A1f 16384 ; after GEMM1 reused as y [z=128][pad 68]
#define OFF_WWB  33792    // 8192
#define OFF_F    41984    // f  [z=128][pad 68]   (68 % 32 == 4)
#define OFF_GP   50688    // gp [j=64][pad 72]    (72 % 32 == 8)
#define OFF_AS   55296    // a[z] 128
#define OFF_BB   55424    // bb[j] 64
#define OFF_BBW  55488    // per-phi-warp bb partials 4*64
#define OFF_GB   55744    // g_b 64
#define OFF_PB   55808    // phi_b 64
#define OFF_WP   55872    // cat_w[64:] 64
#define OFF_AL   55936    // alpha 128
#define OFF_BE   56064    // beta 128
#define OFF_VT   56192    // vt 128
#define SMEM_FLOATS 56320
#define SMEM_BYTES (SMEM_FLOATS * 4)   // 225280

__global__ void __launch_bounds__(THREADS, 1)
nonlocal_kernel(const float* __restrict__ x,
                const float* __restrict__ g_b,
                const float* __restrict__ phi_b,
                const float* __restrict__ cat_w,
                float* __restrict__ out)
{
    extern __shared__ float sm[];
    const int tid  = threadIdx.x;
    const int lane = tid & 31;
    const int wid  = tid >> 5;     // 0..7 = M-strip
    const int q    = lane & 3;
    const int l4   = lane >> 2;

    const int n  = blockIdx.x;
    const int b  = n >> 10;
    const int wh = n & 1023;
    const float* xg = x + ((size_t)b * 16777216 + (size_t)wh * 128);  // + Ci*131072 + z

    // ---- stage A: loads ----
    {
        const float4* xg4 = (const float4*)xg;
        #pragma unroll
        for (int it = 0; it < 16; it++) {
            int idx = it * 256 + tid;            // 4096 float4
            int Ci = idx >> 5, z4 = idx & 31;
            *(float4*)(sm + OFF_X + Ci * 136 + z4 * 4) = xg4[(size_t)Ci * 32768 + z4];
        }
        const float4* gA = (const float4*)d_A1f;
        float4* sA = (float4*)(sm + OFF_A1);
        #pragma unroll
        for (int it = 0; it < 16; it++) sA[it * 256 + tid] = gA[it * 256 + tid];
        const float4* gW = (const float4*)d_WwB;
        float4* sW = (float4*)(sm + OFF_WWB);
        #pragma unroll
        for (int it = 0; it < 8; it++)  sW[it * 256 + tid] = gW[it * 256 + tid];
    }
    if (tid < 128) { sm[OFF_VT + tid] = d_vt[tid]; sm[OFF_AL + tid] = d_alpha[tid]; sm[OFF_BE + tid] = d_beta[tid]; }
    if (tid < 64)  { sm[OFF_GB + tid] = g_b[tid]; sm[OFF_PB + tid] = phi_b[tid]; sm[OFF_WP + tid] = cat_w[64 + tid]; }
    __syncthreads();

    // ---- a[z] = ct + vt . x[:,z]  (cheap scalar; theta conv collapsed) ----
    if (tid < 128) {
        float s = d_ct;
        #pragma unroll 8
        for (int Ci = 0; Ci < 128; Ci++)
            s = fmaf(sm[OFF_VT + Ci], sm[OFF_X + Ci * 136 + tid], s);
        sm[OFF_AS + tid] = s;
    }

    // ---- GEMM1: D1[o][z], warp strip o = 16*wid..+15 ----
    float d1[16][4];
    #pragma unroll
    for (int nt = 0; nt < 16; nt++)
        #pragma unroll
        for (int r = 0; r < 4; r++) d1[nt][r] = 0.f;

    #pragma unroll 1
    for (int ks = 0; ks < 16; ks++) {
        float4 af = *(const float4*)(sm + OFF_A1 + wid * 2048 + ks * 128 + lane * 4);
        uint32_t a0 = __float_as_uint(af.x), a1 = __float_as_uint(af.y);
        uint32_t a2 = __float_as_uint(af.z), a3 = __float_as_uint(af.w);
        const float* xr0 = sm + OFF_X + (8 * ks + q) * 136 + l4;
        const float* xr1 = xr0 + 4 * 136;
        #pragma unroll
        for (int nt = 0; nt < 16; nt++) {
            uint32_t b0 = __float_as_uint(xr0[8 * nt]);
            uint32_t b1 = __float_as_uint(xr1[8 * nt]);
            mma8(d1[nt], a0, a1, a2, a3, b0, b1);
        }
    }

    // ---- epi1: pool z-pairs in-register (c0/c1 are z=2q,2q+1) ----
    if (wid < 4) {                       // g rows -> gp[j][c], prescaled 1/64
        const int o0 = wid * 16 + l4, o1 = o0 + 8;
        const float gb0 = sm[OFF_GB + o0], gb1 = sm[OFF_GB + o1];
        #pragma unroll
        for (int nt = 0; nt < 16; nt++) {
            int j = 4 * nt + q;
            sm[OFF_GP + j * 72 + o0] = (fmaxf(d1[nt][0], d1[nt][1]) + gb0) * 0.015625f;
            sm[OFF_GP + j * 72 + o1] = (fmaxf(d1[nt][2], d1[nt][3]) + gb1) * 0.015625f;
        }
    } else {                             // phi rows -> bb partials via shfl reduce
        const int o0 = (wid - 4) * 16 + l4, o1 = o0 + 8;
        const float wp0 = sm[OFF_WP + o0], pb0 = sm[OFF_PB + o0];
        const float wp1 = sm[OFF_WP + o1], pb1 = sm[OFF_PB + o1];
        #pragma unroll
        for (int nt = 0; nt < 16; nt++) {
            float v = wp0 * (fmaxf(d1[nt][0], d1[nt][1]) + pb0)
                    + wp1 * (fmaxf(d1[nt][2], d1[nt][3]) + pb1);
            v += __shfl_xor_sync(0xFFFFFFFFu, v, 16);
            v += __shfl_xor_sync(0xFFFFFFFFu, v, 8);
            v += __shfl_xor_sync(0xFFFFFFFFu, v, 4);
            if (l4 == 0) sm[OFF_BBW + (wid - 4) * 64 + 4 * nt + q] = v;
        }
    }
    __syncthreads();
    if (tid < 64) {
        float s = sm[OFF_BBW + tid] + sm[OFF_BBW + 64 + tid]
                + sm[OFF_BBW + 128 + tid] + sm[OFF_BBW + 192 + tid];
        sm[OFF_BB + tid] = s;
    }
    __syncthreads();
    {   // f[z][j] = relu(a[z] + bb[j])
        const int z = tid >> 1, half = tid & 1;
        const float az = sm[OFF_AS + z];
        #pragma unroll
        for (int jj = 0; jj < 8; jj++) {
            int j = half * 32 + 4 * jj;
            float4 v;
            v.x = fmaxf(az + sm[OFF_BB + j + 0], 0.f);
            v.y = fmaxf(az + sm[OFF_BB + j + 1], 0.f);
            v.z = fmaxf(az + sm[OFF_BB + j + 2], 0.f);
            v.w = fmaxf(az + sm[OFF_BB + j + 3], 0.f);
            *(float4*)(sm + OFF_F + z * 68 + j) = v;
        }
    }
    __syncthreads();

    // ---- GEMM2: D2[z][c] = f @ gp, warp strip z = 16*wid..+15 ----
    float d2[8][4];
    #pragma unroll
    for (int nt = 0; nt < 8; nt++)
        #pragma unroll
        for (int r = 0; r < 4; r++) d2[nt][r] = 0.f;

    #pragma unroll 1
    for (int ks = 0; ks < 8; ks++) {
        const float* fr = sm + OFF_F + (16 * wid + l4) * 68 + 8 * ks + q;
        uint32_t a0 = __float_as_uint(fr[0]);
        uint32_t a1 = __float_as_uint(fr[8 * 68]);
        uint32_t a2 = __float_as_uint(fr[4]);
        uint32_t a3 = __float_as_uint(fr[8 * 68 + 4]);
        const float* gr0 = sm + OFF_GP + (8 * ks + q) * 72 + l4;
        const float* gr1 = gr0 + 4 * 72;
        #pragma unroll
        for (int nt = 0; nt < 8; nt++) {
            uint32_t b0 = __float_as_uint(gr0[8 * nt]);
            uint32_t b1 = __float_as_uint(gr1[8 * nt]);
            mma8(d2[nt], a0, a1, a2, a3, b0, b1);
        }
    }

    // ---- epi2: y[z][c] into smem (overwrites dead A1f region; own strip only) ----
    {
        float* yb = sm + OFF_A1;
        #pragma unroll
        for (int nt = 0; nt < 8; nt++) {
            int c = 8 * nt + 2 * q;
            *(float2*)(yb + (16 * wid + l4) * 68 + c)     = make_float2(d2[nt][0], d2[nt][1]);
            *(float2*)(yb + (16 * wid + l4 + 8) * 68 + c) = make_float2(d2[nt][2], d2[nt][3]);
        }
    }
    __syncwarp();

    // ---- GEMM3: D3[z][Co] = y @ Ww^T ----
    float d3[16][4];
    #pragma unroll
    for (int nt = 0; nt < 16; nt++)
        #pragma unroll
        for (int r = 0; r < 4; r++) d3[nt][r] = 0.f;

    #pragma unroll 1
    for (int ks = 0; ks < 8; ks++) {
        const float* yr = sm + OFF_A1 + (16 * wid + l4) * 68 + 8 * ks + q;
        uint32_t a0 = __float_as_uint(yr[0]);
        uint32_t a1 = __float_as_uint(yr[8 * 68]);
        uint32_t a2 = __float_as_uint(yr[4]);
        uint32_t a3 = __float_as_uint(yr[8 * 68 + 4]);
        #pragma unroll
        for (int nt = 0; nt < 16; nt++) {
            float2 bw = *(const float2*)(sm + OFF_WWB + ((ks * 16 + nt) * 32 + lane) * 2);
            mma8(d3[nt], a0, a1, a2, a3,
                 __float_as_uint(bw.x), __float_as_uint(bw.y));
        }
    }

    // ---- epi3: out = D3*alpha + beta + x (residual from smem) ----
    {
        const size_t base = (size_t)b * 16777216 + (size_t)wh * 128;
        const int z0 = 16 * wid + l4, z1 = z0 + 8;
        #pragma unroll
        for (int nt = 0; nt < 16; nt++) {
            int Co0 = 8 * nt + 2 * q, Co1 = Co0 + 1;
            float al0 = sm[OFF_AL + Co0], be0 = sm[OFF_BE + Co0];
            float al1 = sm[OFF_AL + Co1], be1 = sm[OFF_BE + Co1];
            out[base + (size_t)Co0 * 131072 + z0] =
                fmaf(d3[nt][0], al0, be0) + sm[OFF_X + Co0 * 136 + z0];
            out[base + (size_t)Co1 * 131072 + z0] =
                fmaf(d3[nt][1], al1, be1) + sm[OFF_X + Co1 * 136 + z0];
            out[base + (size_t)Co0 * 131072 + z1] =
                fmaf(d3[nt][2], al0, be0) + sm[OFF_X + Co0 * 136 + z1];
            out[base + (size_t)Co1 * 131072 + z1] =
                fmaf(d3[nt][3], al1, be1) + sm[OFF_X + Co1 * 136 + z1];
        }
    }
}

extern "C" void kernel_launch(void* const* d_in, const int* in_sizes, int n_in,
                              void* d_out, int out_size)
{
    const float* x       = (const float*)d_in[0];
    const float* g_w     = (const float*)d_in[1];
    const float* g_b     = (const float*)d_in[2];
    const float* theta_w = (const float*)d_in[3];
    const float* theta_b = (const float*)d_in[4];
    const float* phi_w   = (const float*)d_in[5];
    const float* phi_b   = (const float*)d_in[6];
    const float* cat_w   = (const float*)d_in[7];
    const float* W_w     = (const float*)d_in[8];
    const float* W_b     = (const float*)d_in[9];
    const float* bn_g    = (const float*)d_in[10];
    const float* bn_b    = (const float*)d_in[11];
    const float* bn_m    = (const float*)d_in[12];
    const float* bn_v    = (const float*)d_in[13];

    cudaFuncSetAttribute(nonlocal_kernel,
                         cudaFuncAttributeMaxDynamicSharedMemorySize, SMEM_BYTES);

    setup_kernel<<<1, 256>>>(theta_w, theta_b, cat_w, W_b,
                             bn_g, bn_b, bn_m, bn_v, g_w, phi_w, W_w);
    nonlocal_kernel<<<N_TILES, THREADS, SMEM_BYTES>>>(x, g_b, phi_b, cat_w,
                                                      (float*)d_out);
}

// round 7
// speedup vs baseline: 2.4371x; 1.2526x over previous
#include <cuda_runtime.h>
#include <cstdint>

// B=2, C=128, IC=64, W=H=32, Z=128, nz=64. 2048 tiles of x[C=128][Z=128].
// Warp-level tf32 mma.sync m16n8k8 (base sm_103 target; tcgen05 is 'a'-gated).
//   GEMM1 D1[o=128][z=128] = Wgp[o][Ci] @ x[Ci][z]   (g rows 0..63, phi 64..127)
//   epi1 (register): pool z-pairs; g -> gp[j][c]/64, phi -> bb[j]; a[z]=vt.x scalar
//   GEMM2 D2[z][c=64] = f @ gp, f = relu(a+bb)
//   GEMM3 D3[z][Co=128] = y @ Ww^T ; out = D3*alpha + beta + x
// R7: 2 CTAs/SM — weights read from global (L2-resident frags), smem 73KB via
// overlay (f/gp/y reuse x region), __launch_bounds__(256,2), 2-D warp tiles.

#define N_TILES 2048
#define THREADS 256

__device__ __forceinline__ float to_tf32(float v) {
    uint32_t u; asm("cvt.rna.tf32.f32 %0, %1;" : "=r"(u) : "f"(v));
    return __uint_as_float(u);
}
__device__ __forceinline__ void mma8(float* d, uint32_t a0, uint32_t a1, uint32_t a2,
                                     uint32_t a3, uint32_t b0, uint32_t b1) {
    asm volatile("mma.sync.aligned.m16n8k8.row.col.f32.tf32.tf32.f32 "
                 "{%0,%1,%2,%3}, {%4,%5,%6,%7}, {%8,%9}, {%0,%1,%2,%3};"
                 : "+f"(d[0]), "+f"(d[1]), "+f"(d[2]), "+f"(d[3])
                 : "r"(a0), "r"(a1), "r"(a2), "r"(a3), "r"(b0), "r"(b1));
}

// ---- precomputed globals ----
__device__ float d_vt[128];      // cat_w[:64]^T @ theta_w (theta conv collapsed)
__device__ float d_ct;
__device__ float d_alpha[128];
__device__ float d_beta[128];
__device__ float d_A1f[16384];   // Wgp frags: [strip8][ks16][lane32][r4] (tf32)
__device__ float d_WwB[8192];    // Ww  frags: [ks8][nt16][lane32][r2]    (tf32)

__global__ void setup_kernel(const float* __restrict__ theta_w,
                             const float* __restrict__ theta_b,
                             const float* __restrict__ cat_w,
                             const float* __restrict__ W_b,
                             const float* __restrict__ bn_g,
                             const float* __restrict__ bn_b,
                             const float* __restrict__ bn_m,
                             const float* __restrict__ bn_v,
                             const float* __restrict__ g_w,
                             const float* __restrict__ phi_w,
                             const float* __restrict__ W_w)
{
    int tid = threadIdx.x;  // 256
    if (tid < 128) {
        float s = 0.f;
        for (int ic = 0; ic < 64; ic++) s += cat_w[ic] * theta_w[ic * 128 + tid];
        d_vt[tid] = s;
        float a = bn_g[tid] * rsqrtf(bn_v[tid] + 1e-5f);
        d_alpha[tid] = a;
        d_beta[tid]  = (W_b[tid] - bn_m[tid]) * a + bn_b[tid];
    }
    if (tid == 0) {
        float s = 0.f;
        for (int ic = 0; ic < 64; ic++) s += cat_w[ic] * theta_b[ic];
        d_ct = s;
    }
    // A frags GEMM1: a0:(row,col) a1:(row+8,col) a2:(row,col+4) a3:(row+8,col+4)
    for (int idx = tid; idx < 16384; idx += 256) {
        int r = idx & 3, lane = (idx >> 2) & 31, ks = (idx >> 7) & 15, s = idx >> 11;
        int o  = s * 16 + (lane >> 2) + (r & 1) * 8;
        int Ci = ks * 8 + (lane & 3) + ((r >> 1) & 1) * 4;
        float v = (o < 64) ? g_w[o * 128 + Ci] : phi_w[(o - 64) * 128 + Ci];
        d_A1f[idx] = to_tf32(v);
    }
    // B frags GEMM3: b0:(k,n) b1:(k+4,n); k=c, n=Co
    for (int idx = tid; idx < 8192; idx += 256) {
        int r = idx & 1, lane = (idx >> 1) & 31, nt = (idx >> 6) & 15, ks = idx >> 10;
        int c  = ks * 8 + (lane & 3) + r * 4;
        int Co = nt * 8 + (lane >> 2);
        d_WwB[idx] = to_tf32(W_w[Co * 64 + c]);
    }
}

// ---- smem layout (floats). x region overlaid by f/gp/y after GEMM1. ----
#define OFF_X    0        // x [Ci=128][136]  (136%32==8, frag reads conflict-free)
#define OFF_F    0        // f/y [z=128][68]  (68%32==4)        -- overlay
#define OFF_GP   8704     // gp [j=64][72]    (72%32==8)        -- overlay
#define OFF_AS   17408    // a[z] 128
#define OFF_BB   17536    // bb[j] 64
#define OFF_BBW  17600    // bb partials 2*64
#define OFF_GB   17728
#define OFF_PB   17792
#define OFF_WP   17856
#define OFF_AL   17920
#define OFF_BE   18048
#define OFF_VT   18176
#define SMEM_FLOATS 18304
#define SMEM_BYTES (SMEM_FLOATS * 4)   // 73216 -> 2 CTAs/SM

__global__ void __launch_bounds__(THREADS, 2)
nonlocal_kernel(const float* __restrict__ x,
                const float* __restrict__ g_b,
                const float* __restrict__ phi_b,
                const float* __restrict__ cat_w,
                float* __restrict__ out)
{
    extern __shared__ float sm[];
    const int tid  = threadIdx.x;
    const int lane = tid & 31;
    const int wid  = tid >> 5;     // 0..7
    const int q    = lane & 3;
    const int l4   = lane >> 2;

    const int n  = blockIdx.x;
    const int b  = n >> 10;
    const int wh = n & 1023;
    const size_t gbase = (size_t)b * 16777216 + (size_t)wh * 128;  // + Ci*131072 + z
    const float* xg = x + gbase;

    // ---- stage A: load x tile + small vectors ----
    {
        const float4* xg4 = (const float4*)xg;
        #pragma unroll
        for (int it = 0; it < 16; it++) {
            int idx = it * 256 + tid;            // 4096 float4
            int Ci = idx >> 5, z4 = idx & 31;
            *(float4*)(sm + OFF_X + Ci * 136 + z4 * 4) = xg4[(size_t)Ci * 32768 + z4];
        }
    }
    if (tid < 128) { sm[OFF_VT + tid] = d_vt[tid]; sm[OFF_AL + tid] = d_alpha[tid]; sm[OFF_BE + tid] = d_beta[tid]; }
    if (tid < 64)  { sm[OFF_GB + tid] = g_b[tid]; sm[OFF_PB + tid] = phi_b[tid]; sm[OFF_WP + tid] = cat_w[64 + tid]; }
    __syncthreads();

    // ---- a[z] = ct + vt . x[:,z]  (scalar; theta conv collapsed) ----
    if (tid < 128) {
        float s = d_ct;
        #pragma unroll 8
        for (int Ci = 0; Ci < 128; Ci++)
            s = fmaf(sm[OFF_VT + Ci], sm[OFF_X + Ci * 136 + tid], s);
        sm[OFF_AS + tid] = s;
    }

    // ---- GEMM1: warp grid 4 o-strips(32) x 2 z-halves(64) ----
    const int oz = wid & 3;        // o-strip of 32: o_base = oz*32
    const int zh = wid >> 2;       // z half: zbase = zh*64
    const int zb = zh * 64;

    float d1[2][8][4];
    #pragma unroll
    for (int mt = 0; mt < 2; mt++)
        #pragma unroll
        for (int nt = 0; nt < 8; nt++)
            #pragma unroll
            for (int r = 0; r < 4; r++) d1[mt][nt][r] = 0.f;

    {
        const float4* gA0 = ((const float4*)d_A1f) + (oz * 2) * 512;     // strip oz*2
        const float4* gA1 = gA0 + 512;                                    // strip oz*2+1
        float4 af0 = gA0[lane], af1 = gA1[lane];
        #pragma unroll 1
        for (int ks = 0; ks < 16; ks++) {
            float4 c0 = af0, c1 = af1;
            if (ks < 15) { af0 = gA0[(ks + 1) * 32 + lane]; af1 = gA1[(ks + 1) * 32 + lane]; }
            uint32_t a00 = __float_as_uint(c0.x), a01 = __float_as_uint(c0.y);
            uint32_t a02 = __float_as_uint(c0.z), a03 = __float_as_uint(c0.w);
            uint32_t a10 = __float_as_uint(c1.x), a11 = __float_as_uint(c1.y);
            uint32_t a12 = __float_as_uint(c1.z), a13 = __float_as_uint(c1.w);
            const float* xr0 = sm + OFF_X + (8 * ks + q) * 136 + zb + l4;
            const float* xr1 = xr0 + 4 * 136;
            #pragma unroll
            for (int nt = 0; nt < 8; nt++) {
                uint32_t b0 = __float_as_uint(xr0[8 * nt]);
                uint32_t b1 = __float_as_uint(xr1[8 * nt]);
                mma8(d1[0][nt], a00, a01, a02, a03, b0, b1);
                mma8(d1[1][nt], a10, a11, a12, a13, b0, b1);
            }
        }
    }
    __syncthreads();   // all GEMM1 reads of x done -> overlay region writable

    // ---- epi1: pool z-pairs in-register; gp (g) / bb partials (phi) ----
    if (oz < 2) {      // g rows: o = oz*32 + 16*mt + l4 (+8)
        #pragma unroll
        for (int mt = 0; mt < 2; mt++) {
            const int o0 = oz * 32 + 16 * mt + l4, o1 = o0 + 8;
            const float gb0 = sm[OFF_GB + o0], gb1 = sm[OFF_GB + o1];
            #pragma unroll
            for (int nt = 0; nt < 8; nt++) {
                int j = zb / 2 + 4 * nt + q;
                sm[OFF_GP + j * 72 + o0] = (fmaxf(d1[mt][nt][0], d1[mt][nt][1]) + gb0) * 0.015625f;
                sm[OFF_GP + j * 72 + o1] = (fmaxf(d1[mt][nt][2], d1[mt][nt][3]) + gb1) * 0.015625f;
            }
        }
    } else {           // phi rows -> bb partials via shfl over l4
        #pragma unroll
        for (int nt = 0; nt < 8; nt++) {
            float v = 0.f;
            #pragma unroll
            for (int mt = 0; mt < 2; mt++) {
                const int o0 = (oz - 2) * 32 + 16 * mt + l4 + 64, o1 = o0 + 8;
                const float wp0 = sm[OFF_WP + o0 - 64], pb0 = sm[OFF_PB + o0 - 64];
                const float wp1 = sm[OFF_WP + o1 - 64], pb1 = sm[OFF_PB + o1 - 64];
                v += wp0 * (fmaxf(d1[mt][nt][0], d1[mt][nt][1]) + pb0)
                   + wp1 * (fmaxf(d1[mt][nt][2], d1[mt][nt][3]) + pb1);
            }
            v += __shfl_xor_sync(0xFFFFFFFFu, v, 16);
            v += __shfl_xor_sync(0xFFFFFFFFu, v, 8);
            v += __shfl_xor_sync(0xFFFFFFFFu, v, 4);
            if (l4 == 0) sm[OFF_BBW + (oz - 2) * 64 + zb / 2 + 4 * nt + q] = v;
        }
    }
    __syncthreads();
    if (tid < 64) sm[OFF_BB + tid] = sm[OFF_BBW + tid] + sm[OFF_BBW + 64 + tid];
    __syncthreads();
    {   // f[z][j] = relu(a[z] + bb[j])  (writes overlay rows 0..127 of F)
        const int z = tid >> 1, half = tid & 1;
        const float az = sm[OFF_AS + z];
        #pragma unroll
        for (int jj = 0; jj < 8; jj++) {
            int j = half * 32 + 4 * jj;
            float4 v;
            v.x = fmaxf(az + sm[OFF_BB + j + 0], 0.f);
            v.y = fmaxf(az + sm[OFF_BB + j + 1], 0.f);
            v.z = fmaxf(az + sm[OFF_BB + j + 2], 0.f);
            v.w = fmaxf(az + sm[OFF_BB + j + 3], 0.f);
            *(float4*)(sm + OFF_F + z * 68 + j) = v;
        }
    }
    __syncthreads();

    // ---- GEMM2: D2[z][c] = f @ gp, warp = z-strip 16 (wid) ----
    float d2[8][4];
    #pragma unroll
    for (int nt = 0; nt < 8; nt++)
        #pragma unroll
        for (int r = 0; r < 4; r++) d2[nt][r] = 0.f;

    #pragma unroll 1
    for (int ks = 0; ks < 8; ks++) {
        const float* fr = sm + OFF_F + (16 * wid + l4) * 68 + 8 * ks + q;
        uint32_t a0 = __float_as_uint(fr[0]);
        uint32_t a1 = __float_as_uint(fr[8 * 68]);
        uint32_t a2 = __float_as_uint(fr[4]);
        uint32_t a3 = __float_as_uint(fr[8 * 68 + 4]);
        const float* gr0 = sm + OFF_GP + (8 * ks + q) * 72 + l4;
        const float* gr1 = gr0 + 4 * 72;
        #pragma unroll
        for (int nt = 0; nt < 8; nt++) {
            uint32_t b0 = __float_as_uint(gr0[8 * nt]);
            uint32_t b1 = __float_as_uint(gr1[8 * nt]);
            mma8(d2[nt], a0, a1, a2, a3, b0, b1);
        }
    }
    // epi2: y overwrites own f strip
    #pragma unroll
    for (int nt = 0; nt < 8; nt++) {
        int c = 8 * nt + 2 * q;
        *(float2*)(sm + OFF_F + (16 * wid + l4) * 68 + c)     = make_float2(d2[nt][0], d2[nt][1]);
        *(float2*)(sm + OFF_F + (16 * wid + l4 + 8) * 68 + c) = make_float2(d2[nt][2], d2[nt][3]);
    }
    __syncthreads();   // y read cross-warp in GEMM3

    // ---- GEMM3: warp grid 4 z-strips(32) x 2 Co-halves(64) ----
    {
        const int zq3 = wid >> 1, ch = wid & 1;
        const int zb3 = zq3 * 32, cob = ch * 64;

        float d3[2][8][4];
        #pragma unroll
        for (int mt = 0; mt < 2; mt++)
            #pragma unroll
            for (int nt = 0; nt < 8; nt++)
                #pragma unroll
                for (int r = 0; r < 4; r++) d3[mt][nt][r] = 0.f;

        const float2* gB = (const float2*)d_WwB;
        #pragma unroll 1
        for (int ks = 0; ks < 8; ks++) {
            const float* yr0 = sm + OFF_F + (zb3 + l4) * 68 + 8 * ks + q;
            const float* yr1 = yr0 + 16 * 68;
            uint32_t a00 = __float_as_uint(yr0[0]);
            uint32_t a01 = __float_as_uint(yr0[8 * 68]);
            uint32_t a02 = __float_as_uint(yr0[4]);
            uint32_t a03 = __float_as_uint(yr0[8 * 68 + 4]);
            uint32_t a10 = __float_as_uint(yr1[0]);
            uint32_t a11 = __float_as_uint(yr1[8 * 68]);
            uint32_t a12 = __float_as_uint(yr1[4]);
            uint32_t a13 = __float_as_uint(yr1[8 * 68 + 4]);
            #pragma unroll
            for (int nt = 0; nt < 8; nt++) {
                float2 bw = gB[(ks * 16 + ch * 8 + nt) * 32 + lane];
                uint32_t b0 = __float_as_uint(bw.x), b1 = __float_as_uint(bw.y);
                mma8(d3[0][nt], a00, a01, a02, a03, b0, b1);
                mma8(d3[1][nt], a10, a11, a12, a13, b0, b1);
            }
        }

        // ---- epi3: out = D3*alpha + beta + x (residual from global/L2) ----
        #pragma unroll
        for (int mt = 0; mt < 2; mt++) {
            const int z0 = zb3 + 16 * mt + l4, z1 = z0 + 8;
            #pragma unroll
            for (int nt = 0; nt < 8; nt++) {
                int Co0 = cob + 8 * nt + 2 * q, Co1 = Co0 + 1;
                float al0 = sm[OFF_AL + Co0], be0 = sm[OFF_BE + Co0];
                float al1 = sm[OFF_AL + Co1], be1 = sm[OFF_BE + Co1];
                size_t p00 = gbase + (size_t)Co0 * 131072 + z0;
                size_t p10 = gbase + (size_t)Co1 * 131072 + z0;
                size_t p01 = gbase + (size_t)Co0 * 131072 + z1;
                size_t p11 = gbase + (size_t)Co1 * 131072 + z1;
                out[p00] = fmaf(d3[mt][nt][0], al0, be0) + __ldg(x + p00);
                out[p10] = fmaf(d3[mt][nt][1], al1, be1) + __ldg(x + p10);
                out[p01] = fmaf(d3[mt][nt][2], al0, be0) + __ldg(x + p01);
                out[p11] = fmaf(d3[mt][nt][3], al1, be1) + __ldg(x + p11);
            }
        }
    }
}

extern "C" void kernel_launch(void* const* d_in, const int* in_sizes, int n_in,
                              void* d_out, int out_size)
{
    const float* x       = (const float*)d_in[0];
    const float* g_w     = (const float*)d_in[1];
    const float* g_b     = (const float*)d_in[2];
    const float* theta_w = (const float*)d_in[3];
    const float* theta_b = (const float*)d_in[4];
    const float* phi_w   = (const float*)d_in[5];
    const float* phi_b   = (const float*)d_in[6];
    const float* cat_w   = (const float*)d_in[7];
    const float* W_w     = (const float*)d_in[8];
    const float* W_b     = (const float*)d_in[9];
    const float* bn_g    = (const float*)d_in[10];
    const float* bn_b    = (const float*)d_in[11];
    const float* bn_m    = (const float*)d_in[12];
    const float* bn_v    = (const float*)d_in[13];

    cudaFuncSetAttribute(nonlocal_kernel,
                         cudaFuncAttributeMaxDynamicSharedMemorySize, SMEM_BYTES);

    setup_kernel<<<1, 256>>>(theta_w, theta_b, cat_w, W_b,
                             bn_g, bn_b, bn_m, bn_v, g_w, phi_w, W_w);
    nonlocal_kernel<<<N_TILES, THREADS, SMEM_BYTES>>>(x, g_b, phi_b, cat_w,
                                                      (float*)d_out);
}